// round 15
// baseline (speedup 1.0000x reference)
#include <cuda_runtime.h>
#include <cuda_bf16.h>
#include <cstdint>
#include <math.h>

#define FULL 0xffffffffu
typedef unsigned long long ull;

// ------------------------ scratch (__device__ globals; no allocs) ------------
__device__ float         g_f1[65536 * 128];   // relu(layer1) of relationship encoder
__device__ unsigned char g_B8[128 * 2240];    // rw1 * 64 quantized to e4m3
__device__ unsigned g_eg[64];
__device__ unsigned g_rg[128];
__device__ float    g_t1[64];
__device__ float    g_w2t[128 * 64];
__device__ float    g_w3t[64 * 32];
__device__ float    g_w4t[32 * 8];
__device__ float    g_ew1t[128 * 32];
__device__ float    g_ew2t[32 * 8];

// ------------------------ helpers -------------------------------------------
__device__ __forceinline__ ull pk2(float lo, float hi) {
    ull r; asm("mov.b64 %0, {%1, %2};" : "=l"(r) : "f"(lo), "f"(hi)); return r;
}
__device__ __forceinline__ void upk2(ull v, float& lo, float& hi) {
    asm("mov.b64 {%0, %1}, %2;" : "=f"(lo), "=f"(hi) : "l"(v));
}
__device__ __forceinline__ void ffma2(ull& d, ull a, ull b) {
    asm("fma.rn.f32x2 %0, %1, %2, %0;" : "+l"(d) : "l"(a), "l"(b));
}
__device__ __forceinline__ unsigned fenc(float f) {
    unsigned u = __float_as_uint(f);
    return (u & 0x80000000u) ? ~u : (u | 0x80000000u);
}
__device__ __forceinline__ float fdec(unsigned u) {
    return (u & 0x80000000u) ? __uint_as_float(u ^ 0x80000000u) : __uint_as_float(~u);
}
#define ENC_NEG_INF 0x007FFFFFu   // fenc(-inf)

// pack 4 consecutive f32 -> 4 e4m3 bytes (x0 in lowest byte)
__device__ __forceinline__ uint32_t pack4_e4m3(float x0, float x1, float x2, float x3) {
    unsigned short lo, hi;
    asm("cvt.rn.satfinite.e4m3x2.f32 %0, %1, %2;" : "=h"(lo) : "f"(x1), "f"(x0));
    asm("cvt.rn.satfinite.e4m3x2.f32 %0, %1, %2;" : "=h"(hi) : "f"(x3), "f"(x2));
    return (uint32_t)lo | ((uint32_t)hi << 16);
}
__device__ __forceinline__ void mma_e4m3(float* c, const unsigned* a, unsigned b0, unsigned b1) {
    asm volatile("mma.sync.aligned.m16n8k32.row.col.f32.e4m3.e4m3.f32 "
        "{%0,%1,%2,%3}, {%4,%5,%6,%7}, {%8,%9}, {%0,%1,%2,%3};"
        : "+f"(c[0]), "+f"(c[1]), "+f"(c[2]), "+f"(c[3])
        : "r"(a[0]), "r"(a[1]), "r"(a[2]), "r"(a[3]), "r"(b0), "r"(b1));
}
#define CP_ASYNC16(dst, src) asm volatile("cp.async.cg.shared.global [%0], [%1], 16;\n" :: "r"(dst), "l"(src))
#define CP_COMMIT            asm volatile("cp.async.commit_group;\n")
#define CP_WAIT(n)           asm volatile("cp.async.wait_group %0;\n" :: "n"(n))
#define STS128(addr, r0, r1, r2, r3) \
    asm volatile("st.shared.v4.b32 [%0], {%1, %2, %3, %4};" \
        :: "r"(addr), "r"(r0), "r"(r1), "r"(r2), "r"(r3) : "memory")

// ------------------------ init ----------------------------------------------
__global__ void k_init() {
    int t = threadIdx.x;
    if (t < 64)  g_eg[t] = ENC_NEG_INF;
    if (t < 128) g_rg[t] = ENC_NEG_INF;
    if (t < 64)  g_t1[t] = 0.f;
}

// ------------------------ weight prep (transposes + fp8 B) -------------------
__global__ void k_prep(const float* __restrict__ rw2, const float* __restrict__ rw3,
                       const float* __restrict__ rw4, const float* __restrict__ ew1,
                       const float* __restrict__ ew2, const float* __restrict__ rw1) {
    int gt = blockIdx.x * blockDim.x + threadIdx.x;
    for (int i = gt; i < 128 * 2240; i += gridDim.x * blockDim.x) {
        float x = rw1[i] * 64.f;
        unsigned short v;
        asm("cvt.rn.satfinite.e4m3x2.f32 %0, %1, %2;" : "=h"(v) : "f"(0.f), "f"(x));
        g_B8[i] = (unsigned char)v;
    }
    if (blockIdx.x == 0) {
        int t = threadIdx.x;
        for (int i = t; i < 64 * 128; i += 256) { int j = i >> 7, k = i & 127; g_w2t[k * 64 + j] = rw2[i]; }
        for (int i = t; i < 32 * 64;  i += 256) { int j = i >> 6, k = i & 63;  g_w3t[k * 32 + j] = rw3[i]; }
        for (int i = t; i < 8 * 32;   i += 256) { int j = i >> 5, k = i & 31;  g_w4t[k * 8 + j]  = rw4[i]; }
        for (int i = t; i < 32 * 128; i += 256) { int j = i >> 7, k = i & 127; g_ew1t[k * 32 + j] = ew1[i]; }
        for (int i = t; i < 8 * 32;   i += 256) { int j = i >> 5, k = i & 31;  g_ew2t[k * 8 + j]  = ew2[i]; }
    }
}

// ------------------------ gemm1: heterogeneous MMA + FFMA split --------------
// Rows [0, 49152): 384 fp8-MMA tiles (legacy tensor path, ~115 TF ceiling).
// Rows [49152, 65536): 128 f32x2-FFMA tiles (FMA pipe, exact fp32).
// Interleaved by blockIdx (bid%4==3 -> FFMA) so both pipes co-reside per SM.
#define G1_TSTRIDE 48                       // bytes per row (32 data + 16 pad)
#define G1_STAGE   (128 * G1_TSTRIDE)       // 6144 B per matrix per stage
#define G1_SMEM_BYTES (6 * G1_STAGE)        // 36864 B (>= FFMA's 16 KB)

__device__ __forceinline__ void gemm_mma_tile(unsigned char* sm8,
                                              const float* __restrict__ A,
                                              const float* __restrict__ bias,
                                              int tile) {
    unsigned char* Asm = sm8;
    unsigned char* Bsm = sm8 + 3 * G1_STAGE;
    const int tid = threadIdx.x;
    const int wid = tid >> 5, lane = tid & 31;
    const int qr = lane >> 2, qc = lane & 3;
    const int wm = (wid & 3) * 32, wn = (wid >> 2) * 64;
    const size_t m0 = (size_t)tile * 128;

    const int arow = tid & 127, ahf = tid >> 7;
    const float* Ag = A + (m0 + arow) * 2240 + ahf * 16;
    const uint32_t a_sm = (uint32_t)__cvta_generic_to_shared(Asm)
                        + (uint32_t)(arow * G1_TSTRIDE + ahf * 16);
    const int brow = tid >> 1, bhf = tid & 1;
    const unsigned char* Bg = g_B8 + brow * 2240 + bhf * 16;
    const uint32_t b_sm = (uint32_t)__cvta_generic_to_shared(Bsm)
                        + (uint32_t)(brow * G1_TSTRIDE + bhf * 16);

    float c[2][8][4];
    #pragma unroll
    for (int i = 0; i < 2; i++)
        #pragma unroll
        for (int j = 0; j < 8; j++)
            #pragma unroll
            for (int q = 0; q < 4; q++) c[i][j][q] = 0.f;

    float4 rg[4];
    #pragma unroll
    for (int i = 0; i < 4; i++) rg[i] = *(const float4*)(Ag + i * 4);
    CP_ASYNC16(b_sm, Bg);
    CP_COMMIT;
    {
        uint32_t w0 = pack4_e4m3(rg[0].x, rg[0].y, rg[0].z, rg[0].w);
        uint32_t w1 = pack4_e4m3(rg[1].x, rg[1].y, rg[1].z, rg[1].w);
        uint32_t w2 = pack4_e4m3(rg[2].x, rg[2].y, rg[2].z, rg[2].w);
        uint32_t w3 = pack4_e4m3(rg[3].x, rg[3].y, rg[3].z, rg[3].w);
        STS128(a_sm, w0, w1, w2, w3);
    }
    #pragma unroll
    for (int i = 0; i < 4; i++) rg[i] = *(const float4*)(Ag + 32 + i * 4);
    CP_ASYNC16(b_sm + G1_STAGE, Bg + 32);
    CP_COMMIT;
    {
        uint32_t w0 = pack4_e4m3(rg[0].x, rg[0].y, rg[0].z, rg[0].w);
        uint32_t w1 = pack4_e4m3(rg[1].x, rg[1].y, rg[1].z, rg[1].w);
        uint32_t w2 = pack4_e4m3(rg[2].x, rg[2].y, rg[2].z, rg[2].w);
        uint32_t w3 = pack4_e4m3(rg[3].x, rg[3].y, rg[3].z, rg[3].w);
        STS128(a_sm + G1_STAGE, w0, w1, w2, w3);
    }
    #pragma unroll
    for (int i = 0; i < 4; i++) rg[i] = *(const float4*)(Ag + 64 + i * 4);

    for (int t = 0; t < 70; t++) {
        CP_WAIT(1);
        __syncthreads();
        const int st = t % 3;
        const unsigned char* Ab = Asm + st * G1_STAGE;
        const unsigned char* Bb = Bsm + st * G1_STAGE;
        unsigned af[2][4];
        #pragma unroll
        for (int i = 0; i < 2; i++) {
            const uint32_t* pa = (const uint32_t*)(Ab + (wm + i * 16 + qr) * G1_TSTRIDE) + qc;
            af[i][0] = pa[0];
            af[i][1] = pa[8 * 12];
            af[i][2] = pa[4];
            af[i][3] = pa[8 * 12 + 4];
        }
        #pragma unroll
        for (int j = 0; j < 8; j++) {
            const uint32_t* pb = (const uint32_t*)(Bb + (wn + j * 8 + qr) * G1_TSTRIDE) + qc;
            unsigned b0 = pb[0], b1 = pb[4];
            mma_e4m3(c[0][j], af[0], b0, b1);
            mma_e4m3(c[1][j], af[1], b0, b1);
        }
        if (t + 2 < 70) {
            const int s2 = (t + 2) % 3;
            uint32_t w0 = pack4_e4m3(rg[0].x, rg[0].y, rg[0].z, rg[0].w);
            uint32_t w1 = pack4_e4m3(rg[1].x, rg[1].y, rg[1].z, rg[1].w);
            uint32_t w2 = pack4_e4m3(rg[2].x, rg[2].y, rg[2].z, rg[2].w);
            uint32_t w3 = pack4_e4m3(rg[3].x, rg[3].y, rg[3].z, rg[3].w);
            STS128(a_sm + s2 * G1_STAGE, w0, w1, w2, w3);
            CP_ASYNC16(b_sm + s2 * G1_STAGE, Bg + (t + 2) * 32);
            if (t + 3 < 70) {
                const float* nap = Ag + (t + 3) * 32;
                #pragma unroll
                for (int i = 0; i < 4; i++) rg[i] = *(const float4*)(nap + i * 4);
            }
        }
        CP_COMMIT;
    }
    // epilogue: descale (B was x64) + bias + relu + store
    #pragma unroll
    for (int j = 0; j < 8; j++) {
        int n = wn + j * 8 + 2 * qc;
        float b0 = __ldg(&bias[n]), b1 = __ldg(&bias[n + 1]);
        #pragma unroll
        for (int i = 0; i < 2; i++) {
            size_t m = m0 + wm + i * 16 + qr;
            float2 v0 = make_float2(fmaxf(c[i][j][0] * 0.015625f + b0, 0.f),
                                    fmaxf(c[i][j][1] * 0.015625f + b1, 0.f));
            float2 v1 = make_float2(fmaxf(c[i][j][2] * 0.015625f + b0, 0.f),
                                    fmaxf(c[i][j][3] * 0.015625f + b1, 0.f));
            *(float2*)(g_f1 + m * 128 + n)       = v0;
            *(float2*)(g_f1 + (m + 8) * 128 + n) = v1;
        }
    }
}

// FFMA tile (exact fp32, f32x2): proven R1 body. Rows 49152 + tile*128.
__device__ __forceinline__ void gemm_ffma_tile(float* sm,
                                               const float* __restrict__ A,
                                               const float* __restrict__ Bw,
                                               const float* __restrict__ bias,
                                               int tile) {
    float* AsF = sm;            // [16][128]
    float* BsF = sm + 2048;     // [16][128]
    const int tid = threadIdx.x;
    const int tx = tid & 15, ty = tid >> 4;
    const size_t m0 = 49152 + (size_t)tile * 128;
    const int lr = tid >> 2;
    const int lc = (tid & 3) * 4;

    const float* Aptr = A + (m0 + lr) * 2240 + lc;
    const float* Bptr = Bw + (size_t)lr * 2240 + lc;

    ull acc[8][4];
    {
        const int cA = tx * 4, cB = 64 + tx * 4;
        ull b01 = pk2(__ldg(&bias[cA]),     __ldg(&bias[cA + 1]));
        ull b23 = pk2(__ldg(&bias[cA + 2]), __ldg(&bias[cA + 3]));
        ull b45 = pk2(__ldg(&bias[cB]),     __ldg(&bias[cB + 1]));
        ull b67 = pk2(__ldg(&bias[cB + 2]), __ldg(&bias[cB + 3]));
        #pragma unroll
        for (int i = 0; i < 8; i++) { acc[i][0] = b01; acc[i][1] = b23; acc[i][2] = b45; acc[i][3] = b67; }
    }

    float4 sa0 = *(const float4*)(Aptr);
    float4 sa1 = *(const float4*)(Aptr + 64 * 2240);
    float4 sb0 = *(const float4*)(Bptr);
    float4 sb1 = *(const float4*)(Bptr + 64 * 2240);

    for (int t = 0; t < 140; t++) {
        #pragma unroll
        for (int j = 0; j < 4; j++) {
            AsF[(lc + j) * 128 + lr]      = ((const float*)&sa0)[j];
            AsF[(lc + j) * 128 + lr + 64] = ((const float*)&sa1)[j];
            BsF[(lc + j) * 128 + lr]      = ((const float*)&sb0)[j];
            BsF[(lc + j) * 128 + lr + 64] = ((const float*)&sb1)[j];
        }
        __syncthreads();
        if (t + 1 < 140) {
            const float* ap = Aptr + (t + 1) * 16;
            const float* bp = Bptr + (t + 1) * 16;
            sa0 = *(const float4*)(ap);
            sa1 = *(const float4*)(ap + 64 * 2240);
            sb0 = *(const float4*)(bp);
            sb1 = *(const float4*)(bp + 64 * 2240);
        }
        const float4* As4 = (const float4*)AsF;
        const float4* Bs4 = (const float4*)BsF;
        #pragma unroll
        for (int k = 0; k < 16; k++) {
            float4 a0 = As4[k * 32 + ty],      a1 = As4[k * 32 + 16 + ty];
            float4 b0 = Bs4[k * 32 + tx],      b1 = Bs4[k * 32 + 16 + tx];
            ull bp0 = pk2(b0.x, b0.y), bp1 = pk2(b0.z, b0.w);
            ull bp2 = pk2(b1.x, b1.y), bp3 = pk2(b1.z, b1.w);
            float av[8] = {a0.x, a0.y, a0.z, a0.w, a1.x, a1.y, a1.z, a1.w};
            #pragma unroll
            for (int i = 0; i < 8; i++) {
                ull ap2 = pk2(av[i], av[i]);
                ffma2(acc[i][0], ap2, bp0);
                ffma2(acc[i][1], ap2, bp1);
                ffma2(acc[i][2], ap2, bp2);
                ffma2(acc[i][3], ap2, bp3);
            }
        }
        __syncthreads();
    }
    #pragma unroll
    for (int i = 0; i < 8; i++) {
        size_t m = m0 + ((i < 4) ? (ty * 4 + i) : (64 + ty * 4 + i - 4));
        float r0, r1, r2, r3;
        upk2(acc[i][0], r0, r1); upk2(acc[i][1], r2, r3);
        float4 v0 = make_float4(fmaxf(r0, 0.f), fmaxf(r1, 0.f), fmaxf(r2, 0.f), fmaxf(r3, 0.f));
        *(float4*)(g_f1 + m * 128 + tx * 4) = v0;
        upk2(acc[i][2], r0, r1); upk2(acc[i][3], r2, r3);
        float4 v1 = make_float4(fmaxf(r0, 0.f), fmaxf(r1, 0.f), fmaxf(r2, 0.f), fmaxf(r3, 0.f));
        *(float4*)(g_f1 + m * 128 + 64 + tx * 4) = v1;
    }
}

__global__ __launch_bounds__(256, 2) void k_gemm1(const float* __restrict__ A,
                                                  const float* __restrict__ Bw,
                                                  const float* __restrict__ bias) {
    extern __shared__ __align__(16) unsigned char smdyn[];
    const int bid = blockIdx.x;
    if ((bid & 3) == 3)
        gemm_ffma_tile((float*)smdyn, A, Bw, bias, bid >> 2);
    else
        gemm_mma_tile(smdyn, A, bias, (bid >> 2) * 3 + (bid & 3));
}

// ------------------------ relationship layers 2..5 + type-max ----------------
#define RMLP_SMEM_FLOATS (8192 + 2048 + 256 + 8 + 128*36 + 64*36)
__global__ __launch_bounds__(256) void k_rmlp(const float* __restrict__ rel,
                                              const float* __restrict__ rb2,
                                              const float* __restrict__ rb3,
                                              const float* __restrict__ rb4,
                                              const float* __restrict__ rb5,
                                              const float* __restrict__ rw5) {
    extern __shared__ float smn[];
    float* w2s = smn;                   // 128*64
    float* w3s = smn + 8192;            // 64*32
    float* w4s = smn + 10240;           // 32*8
    float* w5s = smn + 10496;           // 8
    float* f1t = smn + 10504;           // [128][36]
    float* f2t = smn + 10504 + 128*36;  // [64][36]
    int tid = threadIdx.x;
    for (int i = tid; i < 8192; i += 256) w2s[i] = g_w2t[i];
    for (int i = tid; i < 2048; i += 256) w3s[i] = g_w3t[i];
    if (tid < 256) w4s[tid] = g_w4t[tid];
    if (tid < 8) w5s[tid] = rw5[tid];
    __syncthreads();

    int w = tid >> 5, lane = tid & 31, w4 = w * 4;
    size_t mbase = (size_t)blockIdx.x * 32 + w4;

    int hit[4];
    #pragma unroll
    for (int r = 0; r < 4; r++) {
        size_t m = mbase + r;
        float4 fv = *(const float4*)(g_f1 + m * 128 + lane * 4);
        f1t[(4 * lane + 0) * 36 + w4 + r] = fv.x;
        f1t[(4 * lane + 1) * 36 + w4 + r] = fv.y;
        f1t[(4 * lane + 2) * 36 + w4 + r] = fv.z;
        f1t[(4 * lane + 3) * 36 + w4 + r] = fv.w;
        float4 tv = *(const float4*)(rel + m * 2240 + lane * 4);
        hit[r] = -1;
        if      (tv.x == 1.f) hit[r] = lane * 4;
        else if (tv.y == 1.f) hit[r] = lane * 4 + 1;
        else if (tv.z == 1.f) hit[r] = lane * 4 + 2;
        else if (tv.w == 1.f) hit[r] = lane * 4 + 3;
    }
    __syncwarp();

    ull acc2[4];
    {
        ull bi = pk2(__ldg(&rb2[2 * lane]), __ldg(&rb2[2 * lane + 1]));
        acc2[0] = bi; acc2[1] = bi; acc2[2] = bi; acc2[3] = bi;
    }
    #pragma unroll 4
    for (int k = 0; k < 128; k++) {
        ull wp = *(const ull*)&w2s[k * 64 + 2 * lane];
        float4 f = *(const float4*)&f1t[k * 36 + w4];
        ffma2(acc2[0], pk2(f.x, f.x), wp);
        ffma2(acc2[1], pk2(f.y, f.y), wp);
        ffma2(acc2[2], pk2(f.z, f.z), wp);
        ffma2(acc2[3], pk2(f.w, f.w), wp);
    }
    #pragma unroll
    for (int r = 0; r < 4; r++) {
        float o0, o1; upk2(acc2[r], o0, o1);
        f2t[(2 * lane) * 36 + w4 + r]     = fmaxf(o0, 0.f);
        f2t[(2 * lane + 1) * 36 + w4 + r] = fmaxf(o1, 0.f);
    }
    __syncwarp();

    float acc3[4];
    { float b3 = __ldg(&rb3[lane]); acc3[0]=b3; acc3[1]=b3; acc3[2]=b3; acc3[3]=b3; }
    #pragma unroll 4
    for (int k = 0; k < 64; k++) {
        float wv = w3s[k * 32 + lane];
        float4 f = *(const float4*)&f2t[k * 36 + w4];
        acc3[0] = fmaf(f.x, wv, acc3[0]);
        acc3[1] = fmaf(f.y, wv, acc3[1]);
        acc3[2] = fmaf(f.z, wv, acc3[2]);
        acc3[3] = fmaf(f.w, wv, acc3[3]);
    }
    float f3v[4];
    #pragma unroll
    for (int r = 0; r < 4; r++) f3v[r] = fmaxf(acc3[r], 0.f);

    float acc4[4];
    { float b4 = __ldg(&rb4[lane & 7]); acc4[0]=b4; acc4[1]=b4; acc4[2]=b4; acc4[3]=b4; }
    #pragma unroll
    for (int k = 0; k < 32; k++) {
        float wv = w4s[k * 8 + (lane & 7)];
        acc4[0] = fmaf(__shfl_sync(FULL, f3v[0], k), wv, acc4[0]);
        acc4[1] = fmaf(__shfl_sync(FULL, f3v[1], k), wv, acc4[1]);
        acc4[2] = fmaf(__shfl_sync(FULL, f3v[2], k), wv, acc4[2]);
        acc4[3] = fmaf(__shfl_sync(FULL, f3v[3], k), wv, acc4[3]);
    }
    float w5v = w5s[lane & 7];
    float b5 = __ldg(&rb5[0]);
    #pragma unroll
    for (int r = 0; r < 4; r++) {
        float p = fmaxf(acc4[r], 0.f) * w5v;
        #pragma unroll
        for (int o = 4; o; o >>= 1) p += __shfl_xor_sync(FULL, p, o);
        float rf = p + b5;
        if (hit[r] >= 0) atomicMax(&g_rg[hit[r]], fenc(rf));
    }
}

// ------------------------ entity encoder + type-max --------------------------
__global__ __launch_bounds__(256) void k_ent(const float* __restrict__ ent,
                                             const float* __restrict__ eb1,
                                             const float* __restrict__ eb2,
                                             const float* __restrict__ ew3,
                                             const float* __restrict__ eb3) {
    __shared__ float w1s[128 * 32];
    __shared__ float w2s[32 * 8];
    __shared__ float w3s[8];
    __shared__ float e1s[8][128];
    int tid = threadIdx.x;
    for (int i = tid; i < 128 * 32; i += 256) w1s[i] = g_ew1t[i];
    for (int i = tid; i < 32 * 8;   i += 256) w2s[i] = g_ew2t[i];
    if (tid < 8) w3s[tid] = ew3[tid];
    __syncthreads();

    int w = tid >> 5, lane = tid & 31;
    int m = blockIdx.x * 8 + w;

    float4 ev = *(const float4*)(ent + (size_t)m * 128 + lane * 4);
    *(float4*)(&e1s[w][lane * 4]) = ev;
    int hit = -1;
    if (lane < 16) {
        if      (ev.x == 1.f) hit = lane * 4;
        else if (ev.y == 1.f) hit = lane * 4 + 1;
        else if (ev.z == 1.f) hit = lane * 4 + 2;
        else if (ev.w == 1.f) hit = lane * 4 + 3;
    }
    __syncwarp();

    float a1 = __ldg(&eb1[lane]);
    #pragma unroll 8
    for (int k = 0; k < 128; k++) a1 = fmaf(e1s[w][k], w1s[k * 32 + lane], a1);
    float f1v = fmaxf(a1, 0.f);

    float a2 = __ldg(&eb2[lane & 7]);
    #pragma unroll
    for (int k = 0; k < 32; k++) {
        float v = __shfl_sync(FULL, f1v, k);
        a2 = fmaf(v, w2s[k * 8 + (lane & 7)], a2);
    }
    a2 = fmaxf(a2, 0.f);

    float p = a2 * w3s[lane & 7];
    #pragma unroll
    for (int o = 4; o; o >>= 1) p += __shfl_xor_sync(FULL, p, o);
    float ef = p + __ldg(&eb3[0]);

    if (hit >= 0) atomicMax(&g_eg[hit], fenc(ef));
}

// ------------------------ target layer 1 (64 x 67712 GEMV, split-K) ----------
__global__ __launch_bounds__(256) void k_tgt(const float* __restrict__ tgt,
                                             const float* __restrict__ tw1) {
    int j = blockIdx.x >> 3, s = blockIdx.x & 7;
    int base = s * 8464;                     // 67712 / 8
    const float* wrow = tw1 + (size_t)j * 67712 + base;
    const float* trow = tgt + base;
    float acc = 0.f;
    for (int i = threadIdx.x * 4; i < 8464; i += 1024) {
        float4 a = *(const float4*)(trow + i);
        float4 b = *(const float4*)(wrow + i);
        acc = fmaf(a.x, b.x, fmaf(a.y, b.y, fmaf(a.z, b.z, fmaf(a.w, b.w, acc))));
    }
    #pragma unroll
    for (int o = 16; o; o >>= 1) acc += __shfl_xor_sync(FULL, acc, o);
    __shared__ float red[8];
    int lane = threadIdx.x & 31, w = threadIdx.x >> 5;
    if (lane == 0) red[w] = acc;
    __syncthreads();
    if (threadIdx.x == 0) {
        float s2 = 0.f;
        #pragma unroll
        for (int i = 0; i < 8; i++) s2 += red[i];
        atomicAdd(&g_t1[j], s2);
    }
}

// ------------------------ target layer2 + GRU + action head + softmax --------
__global__ __launch_bounds__(384) void k_final(const float* __restrict__ tb1,
                                               const float* __restrict__ tw2,
                                               const float* __restrict__ tb2,
                                               const float* __restrict__ wih,
                                               const float* __restrict__ whh,
                                               const float* __restrict__ bih,
                                               const float* __restrict__ bhh,
                                               const float* __restrict__ hidden,
                                               const float* __restrict__ aw,
                                               const float* __restrict__ ab,
                                               const float* __restrict__ mask,
                                               float* __restrict__ out) {
    __shared__ float t1s[64];
    __shared__ float env[208];
    __shared__ float gxs[384], ghs[384];
    __shared__ float hs[128];
    __shared__ float ls[256];
    __shared__ float s_mx, s_sum;
    int t = threadIdx.x;

    if (t < 64) t1s[t] = fmaxf(g_t1[t] + tb1[t], 0.f);
    if (t < 64) { unsigned u = g_eg[t]; env[t] = (u == ENC_NEG_INF) ? 0.f : fdec(u); }
    if (t >= 64 && t < 192) { unsigned u = g_rg[t - 64]; env[t] = (u == ENC_NEG_INF) ? 0.f : fdec(u); }
    __syncthreads();
    if (t < 16) {
        float a = tb2[t];
        for (int k = 0; k < 64; k++) a = fmaf(t1s[k], tw2[t * 64 + k], a);
        env[192 + t] = a;
    }
    __syncthreads();
    {
        float gx = bih[t];
        for (int k = 0; k < 208; k++) gx = fmaf(env[k], wih[t * 208 + k], gx);
        float gh = bhh[t];
        for (int k = 0; k < 128; k++) gh = fmaf(hidden[k], whh[t * 128 + k], gh);
        gxs[t] = gx; ghs[t] = gh;
    }
    __syncthreads();
    if (t < 128) {
        float r = 1.f / (1.f + expf(-(gxs[t] + ghs[t])));
        float z = 1.f / (1.f + expf(-(gxs[128 + t] + ghs[128 + t])));
        float n = tanhf(gxs[256 + t] + r * ghs[256 + t]);
        hs[t] = (1.f - z) * n + z * hidden[t];
    }
    __syncthreads();
    if (t < 256) {
        float a = ab[t];
        for (int k = 0; k < 128; k++) a = fmaf(hs[k], aw[t * 128 + k], a);
        ls[t] = a;
    }
    __syncthreads();
    if (t == 0) {
        float mx = -3.4e38f;
        for (int i = 0; i < 256; i++) mx = fmaxf(mx, ls[i]);
        float sm = 0.f;
        for (int i = 0; i < 256; i++) sm += expf(ls[i] - mx);
        s_mx = mx; s_sum = sm;
    }
    __syncthreads();
    if (t < 256) out[t] = expf(ls[t] - s_mx) / s_sum * mask[t];
}

// ------------------------ launch ---------------------------------------------
extern "C" void kernel_launch(void* const* d_in, const int* in_sizes, int n_in,
                              void* d_out, int out_size) {
    const float* entity = (const float*)d_in[0];
    const float* rel    = (const float*)d_in[1];
    const float* target = (const float*)d_in[2];
    const float* mask   = (const float*)d_in[3];
    const float* ew1 = (const float*)d_in[4],  *eb1 = (const float*)d_in[5];
    const float* ew2 = (const float*)d_in[6],  *eb2 = (const float*)d_in[7];
    const float* ew3 = (const float*)d_in[8],  *eb3 = (const float*)d_in[9];
    const float* rw1 = (const float*)d_in[10], *rb1 = (const float*)d_in[11];
    const float* rw2 = (const float*)d_in[12], *rb2 = (const float*)d_in[13];
    const float* rw3 = (const float*)d_in[14], *rb3 = (const float*)d_in[15];
    const float* rw4 = (const float*)d_in[16], *rb4 = (const float*)d_in[17];
    const float* rw5 = (const float*)d_in[18], *rb5 = (const float*)d_in[19];
    const float* tw1 = (const float*)d_in[20], *tb1 = (const float*)d_in[21];
    const float* tw2 = (const float*)d_in[22], *tb2 = (const float*)d_in[23];
    const float* wih = (const float*)d_in[24], *whh = (const float*)d_in[25];
    const float* bih = (const float*)d_in[26], *bhh = (const float*)d_in[27];
    const float* hidden = (const float*)d_in[28];
    const float* aw  = (const float*)d_in[29], *ab = (const float*)d_in[30];
    float* out = (float*)d_out;

    static_assert(G1_SMEM_BYTES <= 48 * 1024, "gemm smem");
    static_assert(RMLP_SMEM_FLOATS * 4 < 228 * 1024, "rmlp smem");
    cudaFuncSetAttribute(k_gemm1, cudaFuncAttributeMaxDynamicSharedMemorySize, G1_SMEM_BYTES);
    cudaFuncSetAttribute(k_rmlp, cudaFuncAttributeMaxDynamicSharedMemorySize,
                         RMLP_SMEM_FLOATS * 4);

    k_init<<<1, 128>>>();
    k_prep<<<120, 256>>>(rw2, rw3, rw4, ew1, ew2, rw1);
    k_gemm1<<<512, 256, G1_SMEM_BYTES>>>(rel, rw1, rb1);
    k_rmlp<<<2048, 256, RMLP_SMEM_FLOATS * 4>>>(rel, rb2, rb3, rb4, rb5, rw5);
    k_ent<<<256, 256>>>(entity, eb1, eb2, ew3, eb3);
    k_tgt<<<512, 256>>>(target, tw1);
    k_final<<<1, 384>>>(tb1, tw2, tb2, wih, whh, bih, bhh, hidden, aw, ab, mask, out);
}

// round 16
// speedup vs baseline: 1.4202x; 1.4202x over previous
#include <cuda_runtime.h>
#include <cuda_bf16.h>
#include <cstdint>
#include <math.h>

#define FULL 0xffffffffu
typedef unsigned long long ull;

// ------------------------ scratch (__device__ globals; no allocs) ------------
__device__ float         g_f1[65536 * 128];   // relu(layer1) of relationship encoder
__device__ unsigned char g_B8[128 * 2240];    // rw1 * 64 quantized to e4m3
__device__ unsigned g_eg[64];
__device__ unsigned g_rg[128];
__device__ float    g_t1[64];
__device__ float    g_w2t[128 * 64];
__device__ float    g_w3t[64 * 32];
__device__ float    g_w4t[32 * 8];
__device__ float    g_ew1t[128 * 32];
__device__ float    g_ew2t[32 * 8];

// ------------------------ helpers -------------------------------------------
__device__ __forceinline__ ull pk2(float lo, float hi) {
    ull r; asm("mov.b64 %0, {%1, %2};" : "=l"(r) : "f"(lo), "f"(hi)); return r;
}
__device__ __forceinline__ void upk2(ull v, float& lo, float& hi) {
    asm("mov.b64 {%0, %1}, %2;" : "=f"(lo), "=f"(hi) : "l"(v));
}
__device__ __forceinline__ void ffma2(ull& d, ull a, ull b) {
    asm("fma.rn.f32x2 %0, %1, %2, %0;" : "+l"(d) : "l"(a), "l"(b));
}
__device__ __forceinline__ unsigned fenc(float f) {
    unsigned u = __float_as_uint(f);
    return (u & 0x80000000u) ? ~u : (u | 0x80000000u);
}
__device__ __forceinline__ float fdec(unsigned u) {
    return (u & 0x80000000u) ? __uint_as_float(u ^ 0x80000000u) : __uint_as_float(~u);
}
#define ENC_NEG_INF 0x007FFFFFu   // fenc(-inf)

// pack 4 consecutive f32 -> 4 e4m3 bytes (x0 in lowest byte)
__device__ __forceinline__ uint32_t pack4_e4m3(float x0, float x1, float x2, float x3) {
    unsigned short lo, hi;
    asm("cvt.rn.satfinite.e4m3x2.f32 %0, %1, %2;" : "=h"(lo) : "f"(x1), "f"(x0));
    asm("cvt.rn.satfinite.e4m3x2.f32 %0, %1, %2;" : "=h"(hi) : "f"(x3), "f"(x2));
    return (uint32_t)lo | ((uint32_t)hi << 16);
}
__device__ __forceinline__ void mma_e4m3(float* c, const unsigned* a, unsigned b0, unsigned b1) {
    asm volatile("mma.sync.aligned.m16n8k32.row.col.f32.e4m3.e4m3.f32 "
        "{%0,%1,%2,%3}, {%4,%5,%6,%7}, {%8,%9}, {%0,%1,%2,%3};"
        : "+f"(c[0]), "+f"(c[1]), "+f"(c[2]), "+f"(c[3])
        : "r"(a[0]), "r"(a[1]), "r"(a[2]), "r"(a[3]), "r"(b0), "r"(b1));
}
#define CP_ASYNC16(dst, src) asm volatile("cp.async.cg.shared.global [%0], [%1], 16;\n" :: "r"(dst), "l"(src))
#define CP_COMMIT            asm volatile("cp.async.commit_group;\n")
#define CP_WAIT(n)           asm volatile("cp.async.wait_group %0;\n" :: "n"(n))
#define STS128(addr, r0, r1, r2, r3) \
    asm volatile("st.shared.v4.b32 [%0], {%1, %2, %3, %4};" \
        :: "r"(addr), "r"(r0), "r"(r1), "r"(r2), "r"(r3) : "memory")

// ------------------------ init ----------------------------------------------
__global__ void k_init() {
    int t = threadIdx.x;
    if (t < 64)  g_eg[t] = ENC_NEG_INF;
    if (t < 128) g_rg[t] = ENC_NEG_INF;
    if (t < 64)  g_t1[t] = 0.f;
}

// ------------------------ weight prep (transposes + fp8 B) -------------------
__global__ void k_prep(const float* __restrict__ rw2, const float* __restrict__ rw3,
                       const float* __restrict__ rw4, const float* __restrict__ ew1,
                       const float* __restrict__ ew2, const float* __restrict__ rw1) {
    int gt = blockIdx.x * blockDim.x + threadIdx.x;
    for (int i = gt; i < 128 * 2240; i += gridDim.x * blockDim.x) {
        float x = rw1[i] * 64.f;
        unsigned short v;
        asm("cvt.rn.satfinite.e4m3x2.f32 %0, %1, %2;" : "=h"(v) : "f"(0.f), "f"(x));
        g_B8[i] = (unsigned char)v;
    }
    if (blockIdx.x == 0) {
        int t = threadIdx.x;
        for (int i = t; i < 64 * 128; i += 256) { int j = i >> 7, k = i & 127; g_w2t[k * 64 + j] = rw2[i]; }
        for (int i = t; i < 32 * 64;  i += 256) { int j = i >> 6, k = i & 63;  g_w3t[k * 32 + j] = rw3[i]; }
        for (int i = t; i < 8 * 32;   i += 256) { int j = i >> 5, k = i & 31;  g_w4t[k * 8 + j]  = rw4[i]; }
        for (int i = t; i < 32 * 128; i += 256) { int j = i >> 7, k = i & 127; g_ew1t[k * 32 + j] = ew1[i]; }
        for (int i = t; i < 8 * 32;   i += 256) { int j = i >> 5, k = i & 31;  g_ew2t[k * 8 + j]  = ew2[i]; }
    }
}

// ------------------------ relationship layer 1 (e4m3 m16n8k32 MMA) -----------
// C[65536x128] = A[65536x2240] @ B[128x2240]^T, bias + relu -> g_f1.
// Block 128x128, k-tile 32, 8 warps (4m x 2n). 5 SMEM stages + depth-2 A reg
// FIFO: LDG at iter t -> STS at t+2 (stage t+4) -> compute at t+4. ~3 iteration
// periods of DRAM-latency slack (vs ~1 in the 3-stage version).
#define G1_TSTRIDE 48                       // bytes per row (32 data + 16 pad)
#define G1_STAGE   (128 * G1_TSTRIDE)       // 6144 B per matrix per stage
#define G1_NSTAGE  5
#define G1_SMEM_BYTES (2 * G1_NSTAGE * G1_STAGE)  // 61440 B

__global__ __launch_bounds__(256, 2) void k_gemm1(const float* __restrict__ A,
                                                  const float* __restrict__ bias) {
    extern __shared__ __align__(16) unsigned char sm8[];
    unsigned char* Asm = sm8;
    unsigned char* Bsm = sm8 + G1_NSTAGE * G1_STAGE;
    const int tid = threadIdx.x;
    const int wid = tid >> 5, lane = tid & 31;
    const int qr = lane >> 2, qc = lane & 3;
    const int wm = (wid & 3) * 32, wn = (wid >> 2) * 64;
    const size_t m0 = (size_t)blockIdx.x * 128;

    // A loader: 16 f32 per thread -> 16 e4m3 (one STS.128)
    const int arow = tid & 127, ahf = tid >> 7;
    const float* Ag = A + (m0 + arow) * 2240 + ahf * 16;
    const uint32_t a_sm = (uint32_t)__cvta_generic_to_shared(Asm)
                        + (uint32_t)(arow * G1_TSTRIDE + ahf * 16);
    // B loader: one 16B cp.async per thread
    const int brow = tid >> 1, bhf = tid & 1;
    const unsigned char* Bg = g_B8 + brow * 2240 + bhf * 16;
    const uint32_t b_sm = (uint32_t)__cvta_generic_to_shared(Bsm)
                        + (uint32_t)(brow * G1_TSTRIDE + bhf * 16);

    float c[2][8][4];
    #pragma unroll
    for (int i = 0; i < 2; i++)
        #pragma unroll
        for (int j = 0; j < 8; j++)
            #pragma unroll
            for (int q = 0; q < 4; q++) c[i][j][q] = 0.f;

    // prologue: fill stages 0..3 (A convert+STS inline; B cp.async, 1 group/stage)
    #pragma unroll
    for (int s = 0; s < 4; s++) {
        float4 t0 = *(const float4*)(Ag + s * 32);
        float4 t1 = *(const float4*)(Ag + s * 32 + 4);
        float4 t2 = *(const float4*)(Ag + s * 32 + 8);
        float4 t3 = *(const float4*)(Ag + s * 32 + 12);
        uint32_t w0 = pack4_e4m3(t0.x, t0.y, t0.z, t0.w);
        uint32_t w1 = pack4_e4m3(t1.x, t1.y, t1.z, t1.w);
        uint32_t w2 = pack4_e4m3(t2.x, t2.y, t2.z, t2.w);
        uint32_t w3 = pack4_e4m3(t3.x, t3.y, t3.z, t3.w);
        STS128(a_sm + s * G1_STAGE, w0, w1, w2, w3);
        CP_ASYNC16(b_sm + s * G1_STAGE, Bg + s * 32);
        CP_COMMIT;
    }
    // depth-2 A register FIFO: rgq[0] -> stage 4 (STS at t=0), rgq[1] -> stage 5 (t=1)
    float4 rgq[2][4];
    #pragma unroll
    for (int i = 0; i < 4; i++) rgq[0][i] = *(const float4*)(Ag + 4 * 32 + i * 4);
    #pragma unroll
    for (int i = 0; i < 4; i++) rgq[1][i] = *(const float4*)(Ag + 5 * 32 + i * 4);

    for (int t = 0; t < 70; t++) {
        CP_WAIT(3);
        __syncthreads();
        const int st = t % G1_NSTAGE;
        const unsigned char* Ab = Asm + st * G1_STAGE;
        const unsigned char* Bb = Bsm + st * G1_STAGE;
        unsigned af[2][4];
        #pragma unroll
        for (int i = 0; i < 2; i++) {
            const uint32_t* pa = (const uint32_t*)(Ab + (wm + i * 16 + qr) * G1_TSTRIDE) + qc;
            af[i][0] = pa[0];
            af[i][1] = pa[8 * 12];
            af[i][2] = pa[4];
            af[i][3] = pa[8 * 12 + 4];
        }
        #pragma unroll
        for (int j = 0; j < 8; j++) {
            const uint32_t* pb = (const uint32_t*)(Bb + (wn + j * 8 + qr) * G1_TSTRIDE) + qc;
            unsigned b0 = pb[0], b1 = pb[4];
            mma_e4m3(c[0][j], af[0], b0, b1);
            mma_e4m3(c[1][j], af[1], b0, b1);
        }
        // fill stage t+4 (== stage read at t-1; safe past the sync at t)
        if (t + 4 < 70) {
            const int s2 = (t + 4) % G1_NSTAGE;
            float4* rg = rgq[t & 1];
            uint32_t w0 = pack4_e4m3(rg[0].x, rg[0].y, rg[0].z, rg[0].w);
            uint32_t w1 = pack4_e4m3(rg[1].x, rg[1].y, rg[1].z, rg[1].w);
            uint32_t w2 = pack4_e4m3(rg[2].x, rg[2].y, rg[2].z, rg[2].w);
            uint32_t w3 = pack4_e4m3(rg[3].x, rg[3].y, rg[3].z, rg[3].w);
            STS128(a_sm + s2 * G1_STAGE, w0, w1, w2, w3);
            CP_ASYNC16(b_sm + s2 * G1_STAGE, Bg + (t + 4) * 32);
            if (t + 6 < 70) {
                const float* nap = Ag + (t + 6) * 32;
                #pragma unroll
                for (int i = 0; i < 4; i++) rgq[t & 1][i] = *(const float4*)(nap + i * 4);
            }
        }
        CP_COMMIT;
    }
    // epilogue: descale (B was x64) + bias + relu + store
    #pragma unroll
    for (int j = 0; j < 8; j++) {
        int n = wn + j * 8 + 2 * qc;
        float b0 = __ldg(&bias[n]), b1 = __ldg(&bias[n + 1]);
        #pragma unroll
        for (int i = 0; i < 2; i++) {
            size_t m = m0 + wm + i * 16 + qr;
            float2 v0 = make_float2(fmaxf(c[i][j][0] * 0.015625f + b0, 0.f),
                                    fmaxf(c[i][j][1] * 0.015625f + b1, 0.f));
            float2 v1 = make_float2(fmaxf(c[i][j][2] * 0.015625f + b0, 0.f),
                                    fmaxf(c[i][j][3] * 0.015625f + b1, 0.f));
            *(float2*)(g_f1 + m * 128 + n)       = v0;
            *(float2*)(g_f1 + (m + 8) * 128 + n) = v1;
        }
    }
}

// ------------------------ relationship layers 2..5 + type-max ----------------
// 4 rows per warp, transposed activation tiles (stride 36 keeps float4 aligned)
#define RMLP_SMEM_FLOATS (8192 + 2048 + 256 + 8 + 128*36 + 64*36)
__global__ __launch_bounds__(256) void k_rmlp(const float* __restrict__ rel,
                                              const float* __restrict__ rb2,
                                              const float* __restrict__ rb3,
                                              const float* __restrict__ rb4,
                                              const float* __restrict__ rb5,
                                              const float* __restrict__ rw5) {
    extern __shared__ float smn[];
    float* w2s = smn;                   // 128*64
    float* w3s = smn + 8192;            // 64*32
    float* w4s = smn + 10240;           // 32*8
    float* w5s = smn + 10496;           // 8
    float* f1t = smn + 10504;           // [128][36]
    float* f2t = smn + 10504 + 128*36;  // [64][36]
    int tid = threadIdx.x;
    for (int i = tid; i < 8192; i += 256) w2s[i] = g_w2t[i];
    for (int i = tid; i < 2048; i += 256) w3s[i] = g_w3t[i];
    if (tid < 256) w4s[tid] = g_w4t[tid];
    if (tid < 8) w5s[tid] = rw5[tid];
    __syncthreads();

    int w = tid >> 5, lane = tid & 31, w4 = w * 4;
    size_t mbase = (size_t)blockIdx.x * 32 + w4;

    int hit[4];
    #pragma unroll
    for (int r = 0; r < 4; r++) {
        size_t m = mbase + r;
        float4 fv = *(const float4*)(g_f1 + m * 128 + lane * 4);
        f1t[(4 * lane + 0) * 36 + w4 + r] = fv.x;
        f1t[(4 * lane + 1) * 36 + w4 + r] = fv.y;
        f1t[(4 * lane + 2) * 36 + w4 + r] = fv.z;
        f1t[(4 * lane + 3) * 36 + w4 + r] = fv.w;
        float4 tv = *(const float4*)(rel + m * 2240 + lane * 4);
        hit[r] = -1;
        if      (tv.x == 1.f) hit[r] = lane * 4;
        else if (tv.y == 1.f) hit[r] = lane * 4 + 1;
        else if (tv.z == 1.f) hit[r] = lane * 4 + 2;
        else if (tv.w == 1.f) hit[r] = lane * 4 + 3;
    }
    __syncwarp();

    ull acc2[4];
    {
        ull bi = pk2(__ldg(&rb2[2 * lane]), __ldg(&rb2[2 * lane + 1]));
        acc2[0] = bi; acc2[1] = bi; acc2[2] = bi; acc2[3] = bi;
    }
    #pragma unroll 4
    for (int k = 0; k < 128; k++) {
        ull wp = *(const ull*)&w2s[k * 64 + 2 * lane];
        float4 f = *(const float4*)&f1t[k * 36 + w4];
        ffma2(acc2[0], pk2(f.x, f.x), wp);
        ffma2(acc2[1], pk2(f.y, f.y), wp);
        ffma2(acc2[2], pk2(f.z, f.z), wp);
        ffma2(acc2[3], pk2(f.w, f.w), wp);
    }
    #pragma unroll
    for (int r = 0; r < 4; r++) {
        float o0, o1; upk2(acc2[r], o0, o1);
        f2t[(2 * lane) * 36 + w4 + r]     = fmaxf(o0, 0.f);
        f2t[(2 * lane + 1) * 36 + w4 + r] = fmaxf(o1, 0.f);
    }
    __syncwarp();

    float acc3[4];
    { float b3 = __ldg(&rb3[lane]); acc3[0]=b3; acc3[1]=b3; acc3[2]=b3; acc3[3]=b3; }
    #pragma unroll 4
    for (int k = 0; k < 64; k++) {
        float wv = w3s[k * 32 + lane];
        float4 f = *(const float4*)&f2t[k * 36 + w4];
        acc3[0] = fmaf(f.x, wv, acc3[0]);
        acc3[1] = fmaf(f.y, wv, acc3[1]);
        acc3[2] = fmaf(f.z, wv, acc3[2]);
        acc3[3] = fmaf(f.w, wv, acc3[3]);
    }
    float f3v[4];
    #pragma unroll
    for (int r = 0; r < 4; r++) f3v[r] = fmaxf(acc3[r], 0.f);

    float acc4[4];
    { float b4 = __ldg(&rb4[lane & 7]); acc4[0]=b4; acc4[1]=b4; acc4[2]=b4; acc4[3]=b4; }
    #pragma unroll
    for (int k = 0; k < 32; k++) {
        float wv = w4s[k * 8 + (lane & 7)];
        acc4[0] = fmaf(__shfl_sync(FULL, f3v[0], k), wv, acc4[0]);
        acc4[1] = fmaf(__shfl_sync(FULL, f3v[1], k), wv, acc4[1]);
        acc4[2] = fmaf(__shfl_sync(FULL, f3v[2], k), wv, acc4[2]);
        acc4[3] = fmaf(__shfl_sync(FULL, f3v[3], k), wv, acc4[3]);
    }
    float w5v = w5s[lane & 7];
    float b5 = __ldg(&rb5[0]);
    #pragma unroll
    for (int r = 0; r < 4; r++) {
        float p = fmaxf(acc4[r], 0.f) * w5v;
        #pragma unroll
        for (int o = 4; o; o >>= 1) p += __shfl_xor_sync(FULL, p, o);
        float rf = p + b5;
        if (hit[r] >= 0) atomicMax(&g_rg[hit[r]], fenc(rf));
    }
}

// ------------------------ entity encoder + type-max --------------------------
__global__ __launch_bounds__(256) void k_ent(const float* __restrict__ ent,
                                             const float* __restrict__ eb1,
                                             const float* __restrict__ eb2,
                                             const float* __restrict__ ew3,
                                             const float* __restrict__ eb3) {
    __shared__ float w1s[128 * 32];
    __shared__ float w2s[32 * 8];
    __shared__ float w3s[8];
    __shared__ float e1s[8][128];
    int tid = threadIdx.x;
    for (int i = tid; i < 128 * 32; i += 256) w1s[i] = g_ew1t[i];
    for (int i = tid; i < 32 * 8;   i += 256) w2s[i] = g_ew2t[i];
    if (tid < 8) w3s[tid] = ew3[tid];
    __syncthreads();

    int w = tid >> 5, lane = tid & 31;
    int m = blockIdx.x * 8 + w;

    float4 ev = *(const float4*)(ent + (size_t)m * 128 + lane * 4);
    *(float4*)(&e1s[w][lane * 4]) = ev;
    int hit = -1;
    if (lane < 16) {
        if      (ev.x == 1.f) hit = lane * 4;
        else if (ev.y == 1.f) hit = lane * 4 + 1;
        else if (ev.z == 1.f) hit = lane * 4 + 2;
        else if (ev.w == 1.f) hit = lane * 4 + 3;
    }
    __syncwarp();

    float a1 = __ldg(&eb1[lane]);
    #pragma unroll 8
    for (int k = 0; k < 128; k++) a1 = fmaf(e1s[w][k], w1s[k * 32 + lane], a1);
    float f1v = fmaxf(a1, 0.f);

    float a2 = __ldg(&eb2[lane & 7]);
    #pragma unroll
    for (int k = 0; k < 32; k++) {
        float v = __shfl_sync(FULL, f1v, k);
        a2 = fmaf(v, w2s[k * 8 + (lane & 7)], a2);
    }
    a2 = fmaxf(a2, 0.f);

    float p = a2 * w3s[lane & 7];
    #pragma unroll
    for (int o = 4; o; o >>= 1) p += __shfl_xor_sync(FULL, p, o);
    float ef = p + __ldg(&eb3[0]);

    if (hit >= 0) atomicMax(&g_eg[hit], fenc(ef));
}

// ------------------------ target layer 1 (64 x 67712 GEMV, split-K) ----------
__global__ __launch_bounds__(256) void k_tgt(const float* __restrict__ tgt,
                                             const float* __restrict__ tw1) {
    int j = blockIdx.x >> 3, s = blockIdx.x & 7;
    int base = s * 8464;                     // 67712 / 8
    const float* wrow = tw1 + (size_t)j * 67712 + base;
    const float* trow = tgt + base;
    float acc = 0.f;
    for (int i = threadIdx.x * 4; i < 8464; i += 1024) {
        float4 a = *(const float4*)(trow + i);
        float4 b = *(const float4*)(wrow + i);
        acc = fmaf(a.x, b.x, fmaf(a.y, b.y, fmaf(a.z, b.z, fmaf(a.w, b.w, acc))));
    }
    #pragma unroll
    for (int o = 16; o; o >>= 1) acc += __shfl_xor_sync(FULL, acc, o);
    __shared__ float red[8];
    int lane = threadIdx.x & 31, w = threadIdx.x >> 5;
    if (lane == 0) red[w] = acc;
    __syncthreads();
    if (threadIdx.x == 0) {
        float s2 = 0.f;
        #pragma unroll
        for (int i = 0; i < 8; i++) s2 += red[i];
        atomicAdd(&g_t1[j], s2);
    }
}

// ------------------------ target layer2 + GRU + action head + softmax --------
__global__ __launch_bounds__(384) void k_final(const float* __restrict__ tb1,
                                               const float* __restrict__ tw2,
                                               const float* __restrict__ tb2,
                                               const float* __restrict__ wih,
                                               const float* __restrict__ whh,
                                               const float* __restrict__ bih,
                                               const float* __restrict__ bhh,
                                               const float* __restrict__ hidden,
                                               const float* __restrict__ aw,
                                               const float* __restrict__ ab,
                                               const float* __restrict__ mask,
                                               float* __restrict__ out) {
    __shared__ float t1s[64];
    __shared__ float env[208];
    __shared__ float gxs[384], ghs[384];
    __shared__ float hs[128];
    __shared__ float ls[256];
    __shared__ float s_mx, s_sum;
    int t = threadIdx.x;

    if (t < 64) t1s[t] = fmaxf(g_t1[t] + tb1[t], 0.f);
    if (t < 64) { unsigned u = g_eg[t]; env[t] = (u == ENC_NEG_INF) ? 0.f : fdec(u); }
    if (t >= 64 && t < 192) { unsigned u = g_rg[t - 64]; env[t] = (u == ENC_NEG_INF) ? 0.f : fdec(u); }
    __syncthreads();
    if (t < 16) {
        float a = tb2[t];
        for (int k = 0; k < 64; k++) a = fmaf(t1s[k], tw2[t * 64 + k], a);
        env[192 + t] = a;
    }
    __syncthreads();
    {
        float gx = bih[t];
        for (int k = 0; k < 208; k++) gx = fmaf(env[k], wih[t * 208 + k], gx);
        float gh = bhh[t];
        for (int k = 0; k < 128; k++) gh = fmaf(hidden[k], whh[t * 128 + k], gh);
        gxs[t] = gx; ghs[t] = gh;
    }
    __syncthreads();
    if (t < 128) {
        float r = 1.f / (1.f + expf(-(gxs[t] + ghs[t])));
        float z = 1.f / (1.f + expf(-(gxs[128 + t] + ghs[128 + t])));
        float n = tanhf(gxs[256 + t] + r * ghs[256 + t]);
        hs[t] = (1.f - z) * n + z * hidden[t];
    }
    __syncthreads();
    if (t < 256) {
        float a = ab[t];
        for (int k = 0; k < 128; k++) a = fmaf(hs[k], aw[t * 128 + k], a);
        ls[t] = a;
    }
    __syncthreads();
    if (t == 0) {
        float mx = -3.4e38f;
        for (int i = 0; i < 256; i++) mx = fmaxf(mx, ls[i]);
        float sm = 0.f;
        for (int i = 0; i < 256; i++) sm += expf(ls[i] - mx);
        s_mx = mx; s_sum = sm;
    }
    __syncthreads();
    if (t < 256) out[t] = expf(ls[t] - s_mx) / s_sum * mask[t];
}

// ------------------------ launch ---------------------------------------------
extern "C" void kernel_launch(void* const* d_in, const int* in_sizes, int n_in,
                              void* d_out, int out_size) {
    const float* entity = (const float*)d_in[0];
    const float* rel    = (const float*)d_in[1];
    const float* target = (const float*)d_in[2];
    const float* mask   = (const float*)d_in[3];
    const float* ew1 = (const float*)d_in[4],  *eb1 = (const float*)d_in[5];
    const float* ew2 = (const float*)d_in[6],  *eb2 = (const float*)d_in[7];
    const float* ew3 = (const float*)d_in[8],  *eb3 = (const float*)d_in[9];
    const float* rw1 = (const float*)d_in[10], *rb1 = (const float*)d_in[11];
    const float* rw2 = (const float*)d_in[12], *rb2 = (const float*)d_in[13];
    const float* rw3 = (const float*)d_in[14], *rb3 = (const float*)d_in[15];
    const float* rw4 = (const float*)d_in[16], *rb4 = (const float*)d_in[17];
    const float* rw5 = (const float*)d_in[18], *rb5 = (const float*)d_in[19];
    const float* tw1 = (const float*)d_in[20], *tb1 = (const float*)d_in[21];
    const float* tw2 = (const float*)d_in[22], *tb2 = (const float*)d_in[23];
    const float* wih = (const float*)d_in[24], *whh = (const float*)d_in[25];
    const float* bih = (const float*)d_in[26], *bhh = (const float*)d_in[27];
    const float* hidden = (const float*)d_in[28];
    const float* aw  = (const float*)d_in[29], *ab = (const float*)d_in[30];
    float* out = (float*)d_out;

    static_assert(G1_SMEM_BYTES <= 64 * 1024, "gemm smem");
    static_assert(RMLP_SMEM_FLOATS * 4 < 228 * 1024, "rmlp smem");
    cudaFuncSetAttribute(k_gemm1, cudaFuncAttributeMaxDynamicSharedMemorySize, G1_SMEM_BYTES);
    cudaFuncSetAttribute(k_rmlp, cudaFuncAttributeMaxDynamicSharedMemorySize,
                         RMLP_SMEM_FLOATS * 4);

    k_init<<<1, 128>>>();
    k_prep<<<120, 256>>>(rw2, rw3, rw4, ew1, ew2, rw1);
    k_gemm1<<<512, 256, G1_SMEM_BYTES>>>(rel, rb1);
    k_rmlp<<<2048, 256, RMLP_SMEM_FLOATS * 4>>>(rel, rb2, rb3, rb4, rb5, rw5);
    k_ent<<<256, 256>>>(entity, eb1, eb2, ew3, eb3);
    k_tgt<<<512, 256>>>(target, tw1);
    k_final<<<1, 384>>>(tb1, tw2, tb2, wih, whh, bih, bhh, hidden, aw, ab, mask, out);
}

// round 17
// speedup vs baseline: 1.7721x; 1.2479x over previous
#include <cuda_runtime.h>
#include <cuda_bf16.h>
#include <cstdint>
#include <math.h>

#define FULL 0xffffffffu
typedef unsigned long long ull;

// ------------------------ scratch (__device__ globals; no allocs) ------------
__device__ float         g_f1[65536 * 128];   // relu(layer1) of relationship encoder
__device__ unsigned char g_B8[128 * 2240];    // rw1 * 64 quantized to e4m3
__device__ unsigned g_eg[64];
__device__ unsigned g_rg[128];
__device__ float    g_t1[64];
__device__ float    g_w2t[128 * 64];
__device__ float    g_w3t[64 * 32];
__device__ float    g_w4t[32 * 8];
__device__ float    g_ew1t[128 * 32];
__device__ float    g_ew2t[32 * 8];

// ------------------------ helpers -------------------------------------------
__device__ __forceinline__ ull pk2(float lo, float hi) {
    ull r; asm("mov.b64 %0, {%1, %2};" : "=l"(r) : "f"(lo), "f"(hi)); return r;
}
__device__ __forceinline__ void upk2(ull v, float& lo, float& hi) {
    asm("mov.b64 {%0, %1}, %2;" : "=f"(lo), "=f"(hi) : "l"(v));
}
__device__ __forceinline__ void ffma2(ull& d, ull a, ull b) {
    asm("fma.rn.f32x2 %0, %1, %2, %0;" : "+l"(d) : "l"(a), "l"(b));
}
__device__ __forceinline__ unsigned fenc(float f) {
    unsigned u = __float_as_uint(f);
    return (u & 0x80000000u) ? ~u : (u | 0x80000000u);
}
__device__ __forceinline__ float fdec(unsigned u) {
    return (u & 0x80000000u) ? __uint_as_float(u ^ 0x80000000u) : __uint_as_float(~u);
}
#define ENC_NEG_INF 0x007FFFFFu   // fenc(-inf)

// pack 4 consecutive f32 -> 4 e4m3 bytes (x0 in lowest byte)
__device__ __forceinline__ uint32_t pack4_e4m3(float x0, float x1, float x2, float x3) {
    unsigned short lo, hi;
    asm("cvt.rn.satfinite.e4m3x2.f32 %0, %1, %2;" : "=h"(lo) : "f"(x1), "f"(x0));
    asm("cvt.rn.satfinite.e4m3x2.f32 %0, %1, %2;" : "=h"(hi) : "f"(x3), "f"(x2));
    return (uint32_t)lo | ((uint32_t)hi << 16);
}
__device__ __forceinline__ void mma_e4m3(float* c, const unsigned* a, unsigned b0, unsigned b1) {
    asm volatile("mma.sync.aligned.m16n8k32.row.col.f32.e4m3.e4m3.f32 "
        "{%0,%1,%2,%3}, {%4,%5,%6,%7}, {%8,%9}, {%0,%1,%2,%3};"
        : "+f"(c[0]), "+f"(c[1]), "+f"(c[2]), "+f"(c[3])
        : "r"(a[0]), "r"(a[1]), "r"(a[2]), "r"(a[3]), "r"(b0), "r"(b1));
}
#define CP_ASYNC16(dst, src) asm volatile("cp.async.cg.shared.global [%0], [%1], 16;\n" :: "r"(dst), "l"(src))
#define CP_COMMIT            asm volatile("cp.async.commit_group;\n")
#define CP_WAIT(n)           asm volatile("cp.async.wait_group %0;\n" :: "n"(n))
#define STS128(addr, r0, r1, r2, r3) \
    asm volatile("st.shared.v4.b32 [%0], {%1, %2, %3, %4};" \
        :: "r"(addr), "r"(r0), "r"(r1), "r"(r2), "r"(r3) : "memory")

// ------------------------ init ----------------------------------------------
__global__ void k_init() {
    int t = threadIdx.x;
    if (t < 64)  g_eg[t] = ENC_NEG_INF;
    if (t < 128) g_rg[t] = ENC_NEG_INF;
    if (t < 64)  g_t1[t] = 0.f;
}

// ------------------------ weight prep (transposes + fp8 B) -------------------
__global__ void k_prep(const float* __restrict__ rw2, const float* __restrict__ rw3,
                       const float* __restrict__ rw4, const float* __restrict__ ew1,
                       const float* __restrict__ ew2, const float* __restrict__ rw1) {
    int gt = blockIdx.x * blockDim.x + threadIdx.x;
    for (int i = gt; i < 128 * 2240; i += gridDim.x * blockDim.x) {
        float x = rw1[i] * 64.f;
        unsigned short v;
        asm("cvt.rn.satfinite.e4m3x2.f32 %0, %1, %2;" : "=h"(v) : "f"(0.f), "f"(x));
        g_B8[i] = (unsigned char)v;
    }
    if (blockIdx.x == 0) {
        int t = threadIdx.x;
        for (int i = t; i < 64 * 128; i += 256) { int j = i >> 7, k = i & 127; g_w2t[k * 64 + j] = rw2[i]; }
        for (int i = t; i < 32 * 64;  i += 256) { int j = i >> 6, k = i & 63;  g_w3t[k * 32 + j] = rw3[i]; }
        for (int i = t; i < 8 * 32;   i += 256) { int j = i >> 5, k = i & 31;  g_w4t[k * 8 + j]  = rw4[i]; }
        for (int i = t; i < 32 * 128; i += 256) { int j = i >> 7, k = i & 127; g_ew1t[k * 32 + j] = ew1[i]; }
        for (int i = t; i < 8 * 32;   i += 256) { int j = i >> 5, k = i & 31;  g_ew2t[k * 8 + j]  = ew2[i]; }
    }
}

// ------------------------ relationship layer 1 (e4m3 m16n8k32 MMA) -----------
// R13 body verbatim: at the legacy-mma.sync hardware ceiling (~116 TF/s).
#define G1_TSTRIDE 48                       // bytes per row (32 data + 16 pad)
#define G1_STAGE   (128 * G1_TSTRIDE)       // 6144 B per matrix per stage
#define G1_SMEM_BYTES (6 * G1_STAGE)        // 3 A + 3 B = 36864 B

__global__ __launch_bounds__(256, 2) void k_gemm1(const float* __restrict__ A,
                                                  const float* __restrict__ bias) {
    extern __shared__ __align__(16) unsigned char sm8[];
    unsigned char* Asm = sm8;
    unsigned char* Bsm = sm8 + 3 * G1_STAGE;
    const int tid = threadIdx.x;
    const int wid = tid >> 5, lane = tid & 31;
    const int qr = lane >> 2, qc = lane & 3;
    const int wm = (wid & 3) * 32, wn = (wid >> 2) * 64;
    const size_t m0 = (size_t)blockIdx.x * 128;

    const int arow = tid & 127, ahf = tid >> 7;
    const float* Ag = A + (m0 + arow) * 2240 + ahf * 16;
    const uint32_t a_sm = (uint32_t)__cvta_generic_to_shared(Asm)
                        + (uint32_t)(arow * G1_TSTRIDE + ahf * 16);
    const int brow = tid >> 1, bhf = tid & 1;
    const unsigned char* Bg = g_B8 + brow * 2240 + bhf * 16;
    const uint32_t b_sm = (uint32_t)__cvta_generic_to_shared(Bsm)
                        + (uint32_t)(brow * G1_TSTRIDE + bhf * 16);

    float c[2][8][4];
    #pragma unroll
    for (int i = 0; i < 2; i++)
        #pragma unroll
        for (int j = 0; j < 8; j++)
            #pragma unroll
            for (int q = 0; q < 4; q++) c[i][j][q] = 0.f;

    float4 rg[4];
    #pragma unroll
    for (int i = 0; i < 4; i++) rg[i] = *(const float4*)(Ag + i * 4);
    CP_ASYNC16(b_sm, Bg);
    CP_COMMIT;
    {
        uint32_t w0 = pack4_e4m3(rg[0].x, rg[0].y, rg[0].z, rg[0].w);
        uint32_t w1 = pack4_e4m3(rg[1].x, rg[1].y, rg[1].z, rg[1].w);
        uint32_t w2 = pack4_e4m3(rg[2].x, rg[2].y, rg[2].z, rg[2].w);
        uint32_t w3 = pack4_e4m3(rg[3].x, rg[3].y, rg[3].z, rg[3].w);
        STS128(a_sm, w0, w1, w2, w3);
    }
    #pragma unroll
    for (int i = 0; i < 4; i++) rg[i] = *(const float4*)(Ag + 32 + i * 4);
    CP_ASYNC16(b_sm + G1_STAGE, Bg + 32);
    CP_COMMIT;
    {
        uint32_t w0 = pack4_e4m3(rg[0].x, rg[0].y, rg[0].z, rg[0].w);
        uint32_t w1 = pack4_e4m3(rg[1].x, rg[1].y, rg[1].z, rg[1].w);
        uint32_t w2 = pack4_e4m3(rg[2].x, rg[2].y, rg[2].z, rg[2].w);
        uint32_t w3 = pack4_e4m3(rg[3].x, rg[3].y, rg[3].z, rg[3].w);
        STS128(a_sm + G1_STAGE, w0, w1, w2, w3);
    }
    #pragma unroll
    for (int i = 0; i < 4; i++) rg[i] = *(const float4*)(Ag + 64 + i * 4);

    for (int t = 0; t < 70; t++) {
        CP_WAIT(1);
        __syncthreads();
        const int st = t % 3;
        const unsigned char* Ab = Asm + st * G1_STAGE;
        const unsigned char* Bb = Bsm + st * G1_STAGE;
        unsigned af[2][4];
        #pragma unroll
        for (int i = 0; i < 2; i++) {
            const uint32_t* pa = (const uint32_t*)(Ab + (wm + i * 16 + qr) * G1_TSTRIDE) + qc;
            af[i][0] = pa[0];
            af[i][1] = pa[8 * 12];
            af[i][2] = pa[4];
            af[i][3] = pa[8 * 12 + 4];
        }
        #pragma unroll
        for (int j = 0; j < 8; j++) {
            const uint32_t* pb = (const uint32_t*)(Bb + (wn + j * 8 + qr) * G1_TSTRIDE) + qc;
            unsigned b0 = pb[0], b1 = pb[4];
            mma_e4m3(c[0][j], af[0], b0, b1);
            mma_e4m3(c[1][j], af[1], b0, b1);
        }
        if (t + 2 < 70) {
            const int s2 = (t + 2) % 3;
            uint32_t w0 = pack4_e4m3(rg[0].x, rg[0].y, rg[0].z, rg[0].w);
            uint32_t w1 = pack4_e4m3(rg[1].x, rg[1].y, rg[1].z, rg[1].w);
            uint32_t w2 = pack4_e4m3(rg[2].x, rg[2].y, rg[2].z, rg[2].w);
            uint32_t w3 = pack4_e4m3(rg[3].x, rg[3].y, rg[3].z, rg[3].w);
            STS128(a_sm + s2 * G1_STAGE, w0, w1, w2, w3);
            CP_ASYNC16(b_sm + s2 * G1_STAGE, Bg + (t + 2) * 32);
            if (t + 3 < 70) {
                const float* nap = Ag + (t + 3) * 32;
                #pragma unroll
                for (int i = 0; i < 4; i++) rg[i] = *(const float4*)(nap + i * 4);
            }
        }
        CP_COMMIT;
    }
    #pragma unroll
    for (int j = 0; j < 8; j++) {
        int n = wn + j * 8 + 2 * qc;
        float b0 = __ldg(&bias[n]), b1 = __ldg(&bias[n + 1]);
        #pragma unroll
        for (int i = 0; i < 2; i++) {
            size_t m = m0 + wm + i * 16 + qr;
            float2 v0 = make_float2(fmaxf(c[i][j][0] * 0.015625f + b0, 0.f),
                                    fmaxf(c[i][j][1] * 0.015625f + b1, 0.f));
            float2 v1 = make_float2(fmaxf(c[i][j][2] * 0.015625f + b0, 0.f),
                                    fmaxf(c[i][j][3] * 0.015625f + b1, 0.f));
            *(float2*)(g_f1 + m * 128 + n)       = v0;
            *(float2*)(g_f1 + (m + 8) * 128 + n) = v1;
        }
    }
}

// ------------------------ relationship layers 2..5 + type-max ----------------
// 8 rows per warp (64 rows/block): halves per-row w2 LDS traffic; activation
// tiles transposed with stride 68 (64 + 4 pad, float4-aligned).
#define RMLP_SMEM_FLOATS (8192 + 2048 + 256 + 8 + 128*68 + 64*68)
__global__ __launch_bounds__(256) void k_rmlp(const float* __restrict__ rel,
                                              const float* __restrict__ rb2,
                                              const float* __restrict__ rb3,
                                              const float* __restrict__ rb4,
                                              const float* __restrict__ rb5,
                                              const float* __restrict__ rw5) {
    extern __shared__ float smn[];
    float* w2s = smn;                   // 128*64
    float* w3s = smn + 8192;            // 64*32
    float* w4s = smn + 10240;           // 32*8
    float* w5s = smn + 10496;           // 8
    float* f1t = smn + 10504;           // [128][68]
    float* f2t = smn + 10504 + 128*68;  // [64][68]
    int tid = threadIdx.x;
    for (int i = tid; i < 8192; i += 256) w2s[i] = g_w2t[i];
    for (int i = tid; i < 2048; i += 256) w3s[i] = g_w3t[i];
    if (tid < 256) w4s[tid] = g_w4t[tid];
    if (tid < 8) w5s[tid] = rw5[tid];
    __syncthreads();

    int w = tid >> 5, lane = tid & 31, w8 = w * 8;
    size_t mbase = (size_t)blockIdx.x * 64 + w8;

    int hit[8];
    #pragma unroll
    for (int r = 0; r < 8; r++) {
        size_t m = mbase + r;
        float4 fv = *(const float4*)(g_f1 + m * 128 + lane * 4);
        f1t[(4 * lane + 0) * 68 + w8 + r] = fv.x;
        f1t[(4 * lane + 1) * 68 + w8 + r] = fv.y;
        f1t[(4 * lane + 2) * 68 + w8 + r] = fv.z;
        f1t[(4 * lane + 3) * 68 + w8 + r] = fv.w;
        float4 tv = *(const float4*)(rel + m * 2240 + lane * 4);
        hit[r] = -1;
        if      (tv.x == 1.f) hit[r] = lane * 4;
        else if (tv.y == 1.f) hit[r] = lane * 4 + 1;
        else if (tv.z == 1.f) hit[r] = lane * 4 + 2;
        else if (tv.w == 1.f) hit[r] = lane * 4 + 3;
    }
    __syncwarp();

    // layer2: lane -> outputs (2*lane, 2*lane+1) for 8 rows
    ull acc2[8];
    {
        ull bi = pk2(__ldg(&rb2[2 * lane]), __ldg(&rb2[2 * lane + 1]));
        #pragma unroll
        for (int r = 0; r < 8; r++) acc2[r] = bi;
    }
    #pragma unroll 4
    for (int k = 0; k < 128; k++) {
        ull wp = *(const ull*)&w2s[k * 64 + 2 * lane];
        float4 fa = *(const float4*)&f1t[k * 68 + w8];
        float4 fb = *(const float4*)&f1t[k * 68 + w8 + 4];
        ffma2(acc2[0], pk2(fa.x, fa.x), wp);
        ffma2(acc2[1], pk2(fa.y, fa.y), wp);
        ffma2(acc2[2], pk2(fa.z, fa.z), wp);
        ffma2(acc2[3], pk2(fa.w, fa.w), wp);
        ffma2(acc2[4], pk2(fb.x, fb.x), wp);
        ffma2(acc2[5], pk2(fb.y, fb.y), wp);
        ffma2(acc2[6], pk2(fb.z, fb.z), wp);
        ffma2(acc2[7], pk2(fb.w, fb.w), wp);
    }
    #pragma unroll
    for (int r = 0; r < 8; r++) {
        float o0, o1; upk2(acc2[r], o0, o1);
        f2t[(2 * lane) * 68 + w8 + r]     = fmaxf(o0, 0.f);
        f2t[(2 * lane + 1) * 68 + w8 + r] = fmaxf(o1, 0.f);
    }
    __syncwarp();

    // layer3: lane -> output lane, 8 rows
    float acc3[8];
    { float b3 = __ldg(&rb3[lane]);
      #pragma unroll
      for (int r = 0; r < 8; r++) acc3[r] = b3; }
    #pragma unroll 4
    for (int k = 0; k < 64; k++) {
        float wv = w3s[k * 32 + lane];
        float4 fa = *(const float4*)&f2t[k * 68 + w8];
        float4 fb = *(const float4*)&f2t[k * 68 + w8 + 4];
        acc3[0] = fmaf(fa.x, wv, acc3[0]);
        acc3[1] = fmaf(fa.y, wv, acc3[1]);
        acc3[2] = fmaf(fa.z, wv, acc3[2]);
        acc3[3] = fmaf(fa.w, wv, acc3[3]);
        acc3[4] = fmaf(fb.x, wv, acc3[4]);
        acc3[5] = fmaf(fb.y, wv, acc3[5]);
        acc3[6] = fmaf(fb.z, wv, acc3[6]);
        acc3[7] = fmaf(fb.w, wv, acc3[7]);
    }
    float f3v[8];
    #pragma unroll
    for (int r = 0; r < 8; r++) f3v[r] = fmaxf(acc3[r], 0.f);

    // layer4 via shuffle; lanes compute output (lane&7)
    float acc4[8];
    { float b4 = __ldg(&rb4[lane & 7]);
      #pragma unroll
      for (int r = 0; r < 8; r++) acc4[r] = b4; }
    #pragma unroll
    for (int k = 0; k < 32; k++) {
        float wv = w4s[k * 8 + (lane & 7)];
        #pragma unroll
        for (int r = 0; r < 8; r++)
            acc4[r] = fmaf(__shfl_sync(FULL, f3v[r], k), wv, acc4[r]);
    }
    float w5v = w5s[lane & 7];
    float b5 = __ldg(&rb5[0]);
    #pragma unroll
    for (int r = 0; r < 8; r++) {
        float p = fmaxf(acc4[r], 0.f) * w5v;
        #pragma unroll
        for (int o = 4; o; o >>= 1) p += __shfl_xor_sync(FULL, p, o);
        float rf = p + b5;
        if (hit[r] >= 0) atomicMax(&g_rg[hit[r]], fenc(rf));
    }
}

// ------------------------ entity encoder + type-max --------------------------
__global__ __launch_bounds__(256) void k_ent(const float* __restrict__ ent,
                                             const float* __restrict__ eb1,
                                             const float* __restrict__ eb2,
                                             const float* __restrict__ ew3,
                                             const float* __restrict__ eb3) {
    __shared__ float w1s[128 * 32];
    __shared__ float w2s[32 * 8];
    __shared__ float w3s[8];
    __shared__ float e1s[8][128];
    int tid = threadIdx.x;
    for (int i = tid; i < 128 * 32; i += 256) w1s[i] = g_ew1t[i];
    for (int i = tid; i < 32 * 8;   i += 256) w2s[i] = g_ew2t[i];
    if (tid < 8) w3s[tid] = ew3[tid];
    __syncthreads();

    int w = tid >> 5, lane = tid & 31;
    int m = blockIdx.x * 8 + w;

    float4 ev = *(const float4*)(ent + (size_t)m * 128 + lane * 4);
    *(float4*)(&e1s[w][lane * 4]) = ev;
    int hit = -1;
    if (lane < 16) {
        if      (ev.x == 1.f) hit = lane * 4;
        else if (ev.y == 1.f) hit = lane * 4 + 1;
        else if (ev.z == 1.f) hit = lane * 4 + 2;
        else if (ev.w == 1.f) hit = lane * 4 + 3;
    }
    __syncwarp();

    float a1 = __ldg(&eb1[lane]);
    #pragma unroll 8
    for (int k = 0; k < 128; k++) a1 = fmaf(e1s[w][k], w1s[k * 32 + lane], a1);
    float f1v = fmaxf(a1, 0.f);

    float a2 = __ldg(&eb2[lane & 7]);
    #pragma unroll
    for (int k = 0; k < 32; k++) {
        float v = __shfl_sync(FULL, f1v, k);
        a2 = fmaf(v, w2s[k * 8 + (lane & 7)], a2);
    }
    a2 = fmaxf(a2, 0.f);

    float p = a2 * w3s[lane & 7];
    #pragma unroll
    for (int o = 4; o; o >>= 1) p += __shfl_xor_sync(FULL, p, o);
    float ef = p + __ldg(&eb3[0]);

    if (hit >= 0) atomicMax(&g_eg[hit], fenc(ef));
}

// ------------------------ target layer 1 (64 x 67712 GEMV, split-K) ----------
__global__ __launch_bounds__(256) void k_tgt(const float* __restrict__ tgt,
                                             const float* __restrict__ tw1) {
    int j = blockIdx.x >> 3, s = blockIdx.x & 7;
    int base = s * 8464;                     // 67712 / 8
    const float* wrow = tw1 + (size_t)j * 67712 + base;
    const float* trow = tgt + base;
    float acc = 0.f;
    for (int i = threadIdx.x * 4; i < 8464; i += 1024) {
        float4 a = *(const float4*)(trow + i);
        float4 b = *(const float4*)(wrow + i);
        acc = fmaf(a.x, b.x, fmaf(a.y, b.y, fmaf(a.z, b.z, fmaf(a.w, b.w, acc))));
    }
    #pragma unroll
    for (int o = 16; o; o >>= 1) acc += __shfl_xor_sync(FULL, acc, o);
    __shared__ float red[8];
    int lane = threadIdx.x & 31, w = threadIdx.x >> 5;
    if (lane == 0) red[w] = acc;
    __syncthreads();
    if (threadIdx.x == 0) {
        float s2 = 0.f;
        #pragma unroll
        for (int i = 0; i < 8; i++) s2 += red[i];
        atomicAdd(&g_t1[j], s2);
    }
}

// ------------------------ target layer2 + GRU + action head + softmax --------
__global__ __launch_bounds__(384) void k_final(const float* __restrict__ tb1,
                                               const float* __restrict__ tw2,
                                               const float* __restrict__ tb2,
                                               const float* __restrict__ wih,
                                               const float* __restrict__ whh,
                                               const float* __restrict__ bih,
                                               const float* __restrict__ bhh,
                                               const float* __restrict__ hidden,
                                               const float* __restrict__ aw,
                                               const float* __restrict__ ab,
                                               const float* __restrict__ mask,
                                               float* __restrict__ out) {
    __shared__ float t1s[64];
    __shared__ float env[208];
    __shared__ float gxs[384], ghs[384];
    __shared__ float hs[128];
    __shared__ float ls[256];
    __shared__ float s_mx, s_sum;
    int t = threadIdx.x;

    if (t < 64) t1s[t] = fmaxf(g_t1[t] + tb1[t], 0.f);
    if (t < 64) { unsigned u = g_eg[t]; env[t] = (u == ENC_NEG_INF) ? 0.f : fdec(u); }
    if (t >= 64 && t < 192) { unsigned u = g_rg[t - 64]; env[t] = (u == ENC_NEG_INF) ? 0.f : fdec(u); }
    __syncthreads();
    if (t < 16) {
        float a = tb2[t];
        for (int k = 0; k < 64; k++) a = fmaf(t1s[k], tw2[t * 64 + k], a);
        env[192 + t] = a;
    }
    __syncthreads();
    {
        float gx = bih[t];
        for (int k = 0; k < 208; k++) gx = fmaf(env[k], wih[t * 208 + k], gx);
        float gh = bhh[t];
        for (int k = 0; k < 128; k++) gh = fmaf(hidden[k], whh[t * 128 + k], gh);
        gxs[t] = gx; ghs[t] = gh;
    }
    __syncthreads();
    if (t < 128) {
        float r = 1.f / (1.f + expf(-(gxs[t] + ghs[t])));
        float z = 1.f / (1.f + expf(-(gxs[128 + t] + ghs[128 + t])));
        float n = tanhf(gxs[256 + t] + r * ghs[256 + t]);
        hs[t] = (1.f - z) * n + z * hidden[t];
    }
    __syncthreads();
    if (t < 256) {
        float a = ab[t];
        for (int k = 0; k < 128; k++) a = fmaf(hs[k], aw[t * 128 + k], a);
        ls[t] = a;
    }
    __syncthreads();
    if (t == 0) {
        float mx = -3.4e38f;
        for (int i = 0; i < 256; i++) mx = fmaxf(mx, ls[i]);
        float sm = 0.f;
        for (int i = 0; i < 256; i++) sm += expf(ls[i] - mx);
        s_mx = mx; s_sum = sm;
    }
    __syncthreads();
    if (t < 256) out[t] = expf(ls[t] - s_mx) / s_sum * mask[t];
}

// ------------------------ launch ---------------------------------------------
extern "C" void kernel_launch(void* const* d_in, const int* in_sizes, int n_in,
                              void* d_out, int out_size) {
    const float* entity = (const float*)d_in[0];
    const float* rel    = (const float*)d_in[1];
    const float* target = (const float*)d_in[2];
    const float* mask   = (const float*)d_in[3];
    const float* ew1 = (const float*)d_in[4],  *eb1 = (const float*)d_in[5];
    const float* ew2 = (const float*)d_in[6],  *eb2 = (const float*)d_in[7];
    const float* ew3 = (const float*)d_in[8],  *eb3 = (const float*)d_in[9];
    const float* rw1 = (const float*)d_in[10], *rb1 = (const float*)d_in[11];
    const float* rw2 = (const float*)d_in[12], *rb2 = (const float*)d_in[13];
    const float* rw3 = (const float*)d_in[14], *rb3 = (const float*)d_in[15];
    const float* rw4 = (const float*)d_in[16], *rb4 = (const float*)d_in[17];
    const float* rw5 = (const float*)d_in[18], *rb5 = (const float*)d_in[19];
    const float* tw1 = (const float*)d_in[20], *tb1 = (const float*)d_in[21];
    const float* tw2 = (const float*)d_in[22], *tb2 = (const float*)d_in[23];
    const float* wih = (const float*)d_in[24], *whh = (const float*)d_in[25];
    const float* bih = (const float*)d_in[26], *bhh = (const float*)d_in[27];
    const float* hidden = (const float*)d_in[28];
    const float* aw  = (const float*)d_in[29], *ab = (const float*)d_in[30];
    float* out = (float*)d_out;

    static_assert(G1_SMEM_BYTES <= 48 * 1024, "gemm smem");
    static_assert(RMLP_SMEM_FLOATS * 4 < 110 * 1024, "rmlp smem");
    cudaFuncSetAttribute(k_gemm1, cudaFuncAttributeMaxDynamicSharedMemorySize, G1_SMEM_BYTES);
    cudaFuncSetAttribute(k_rmlp, cudaFuncAttributeMaxDynamicSharedMemorySize,
                         RMLP_SMEM_FLOATS * 4);

    k_init<<<1, 128>>>();
    k_prep<<<120, 256>>>(rw2, rw3, rw4, ew1, ew2, rw1);
    k_gemm1<<<512, 256, G1_SMEM_BYTES>>>(rel, rb1);
    k_rmlp<<<1024, 256, RMLP_SMEM_FLOATS * 4>>>(rel, rb2, rb3, rb4, rb5, rw5);
    k_ent<<<256, 256>>>(entity, eb1, eb2, ew3, eb3);
    k_tgt<<<512, 256>>>(target, tw1);
    k_final<<<1, 384>>>(tb1, tw2, tb2, wih, whh, bih, bhh, hidden, aw, ab, mask, out);
}